// round 3
// baseline (speedup 1.0000x reference)
#include <cuda_runtime.h>
#include <cuda_bf16.h>
#include <cstdint>

// SoftPixelRadiusCNN:
//   d      = sqrt(distsq + EPS)
//   w_i(k) = exp(-scaler * (d_k - i/length_scale)^2),  scaler = 10*ls*SUBDIV
//   out[v, i*F + f] = sum_k w_i(k) * features[nidx[v,k], f] / (sum_k w_i(k) + EPS)
// V=100000, K=32, F=64, SUBDIV=3. One warp per vertex; lane L owns feature
// columns {2L, 2L+1}; lane k owns neighbor k's distance/weights.

#define K_NEIGH 32
#define F_DIM   64
#define SUBDIV  3
#define EPSV    1e-6f
#define OUT_F   (SUBDIV * F_DIM)

__global__ __launch_bounds__(256)
void softpixel_kernel(const float* __restrict__ features,
                      const float* __restrict__ distsq,
                      const int*   __restrict__ nidx,
                      const float* __restrict__ ls_ptr,
                      float*       __restrict__ out,
                      int V)
{
    const int lane     = threadIdx.x & 31;
    const int warp0    = (blockIdx.x * blockDim.x + threadIdx.x) >> 5;
    const int nwarps   = (gridDim.x * blockDim.x) >> 5;

    const float ls     = __ldg(ls_ptr);
    const float scaler = 10.0f * ls * (float)SUBDIV;
    const float inv_ls = 1.0f / ls;

    for (int v = warp0; v < V; v += nwarps) {
        // --- per-lane neighbor (k = lane): distance, index, 3 bin weights ---
        const float dsq    = __ldg(distsq + (size_t)v * K_NEIGH + lane);
        const int   my_idx = __ldg(nidx   + (size_t)v * K_NEIGH + lane);
        const float d  = sqrtf(dsq + EPSV);
        const float t1 = d - inv_ls;
        const float t2 = d - 2.0f * inv_ls;
        float w0 = __expf(-scaler * d  * d);
        float w1 = __expf(-scaler * t1 * t1);
        float w2 = __expf(-scaler * t2 * t2);

        // --- warp-reduce denominators ---
        float s0 = w0, s1 = w1, s2 = w2;
        #pragma unroll
        for (int off = 16; off > 0; off >>= 1) {
            s0 += __shfl_xor_sync(0xFFFFFFFFu, s0, off);
            s1 += __shfl_xor_sync(0xFFFFFFFFu, s1, off);
            s2 += __shfl_xor_sync(0xFFFFFFFFu, s2, off);
        }
        const float r0 = 1.0f / (s0 + EPSV);
        const float r1 = 1.0f / (s1 + EPSV);
        const float r2 = 1.0f / (s2 + EPSV);

        // --- fused gather + 3-bin accumulate; lane covers cols [2L, 2L+1] ---
        float2 a0 = make_float2(0.f, 0.f);
        float2 a1 = make_float2(0.f, 0.f);
        float2 a2 = make_float2(0.f, 0.f);
        const float* fbase = features + (size_t)2 * lane;

        #pragma unroll
        for (int k = 0; k < K_NEIGH; ++k) {
            const int ik = __shfl_sync(0xFFFFFFFFu, my_idx, k);
            const float2 f = *reinterpret_cast<const float2*>(fbase + (size_t)ik * F_DIM);
            const float b0 = __shfl_sync(0xFFFFFFFFu, w0, k);
            const float b1 = __shfl_sync(0xFFFFFFFFu, w1, k);
            const float b2 = __shfl_sync(0xFFFFFFFFu, w2, k);
            a0.x = fmaf(b0, f.x, a0.x);  a0.y = fmaf(b0, f.y, a0.y);
            a1.x = fmaf(b1, f.x, a1.x);  a1.y = fmaf(b1, f.y, a1.y);
            a2.x = fmaf(b2, f.x, a2.x);  a2.y = fmaf(b2, f.y, a2.y);
        }

        // --- write (V, 3*F): three coalesced float2 stores ---
        float* obase = out + (size_t)v * OUT_F + 2 * lane;
        *reinterpret_cast<float2*>(obase)             = make_float2(a0.x * r0, a0.y * r0);
        *reinterpret_cast<float2*>(obase + F_DIM)     = make_float2(a1.x * r1, a1.y * r1);
        *reinterpret_cast<float2*>(obase + 2 * F_DIM) = make_float2(a2.x * r2, a2.y * r2);
    }
}

extern "C" void kernel_launch(void* const* d_in, const int* in_sizes, int n_in,
                              void* d_out, int out_size)
{
    const float* features = (const float*)d_in[0];
    const float* distsq   = (const float*)d_in[1];
    const int*   nidx     = (const int*)  d_in[2];
    const float* ls       = (const float*)d_in[3];
    float*       out      = (float*)d_out;

    // V from output size (out = V x SUBDIV*F); fall back to distsq size.
    int V = out_size / OUT_F;
    if (V <= 0) V = in_sizes[1] / K_NEIGH;

    const int threads = 256;                 // 8 warps/block, 8 vertices/block
    int blocks = (V * 32 + threads - 1) / threads;
    if (blocks < 1) blocks = 1;
    softpixel_kernel<<<blocks, threads>>>(features, distsq, nidx, ls, out, V);
}

// round 6
// speedup vs baseline: 1.3573x; 1.3573x over previous
#include <cuda_runtime.h>
#include <cuda_bf16.h>
#include <cstdint>

// SoftPixelRadiusCNN:
//   d      = sqrt(distsq + EPS)
//   w_i(k) = exp(-scaler * (d_k - i/ls)^2),  scaler = 10*ls*SUBDIV
//   out[v, i*F + f] = sum_k w_i(k) * features[nidx[v,k], f] / (sum_k w_i(k) + EPS)
// V=100000, K=32, F=64, SUBDIV=3.
//
// One warp per vertex. lane = (half, t), half = lane>>4, t = lane&15.
// Each half-warp covers a FULL feature row (16 lanes x float4 = 64 cols).
// Iteration j handles neighbor 2j (half 0) and 2j+1 (half 1) simultaneously:
// 16 iterations x 4 SHFL broadcasts instead of 32 x 4. R2 profile showed the
// binder is L1TEX/MIO slot throughput (73%) dominated by SHFL count.

#define K_NEIGH 32
#define F_DIM   64
#define SUBDIV  3
#define EPSV    1e-6f
#define OUT_F   (SUBDIV * F_DIM)
#define FULLM   0xFFFFFFFFu

__global__ __launch_bounds__(256)
void softpixel_kernel(const float* __restrict__ features,
                      const float* __restrict__ distsq,
                      const int*   __restrict__ nidx,
                      const float* __restrict__ ls_ptr,
                      float*       __restrict__ out,
                      int V)
{
    const int lane   = threadIdx.x & 31;
    const int half   = lane >> 4;      // 0 or 1
    const int t      = lane & 15;      // float4 column group within the half
    const int warp0  = (blockIdx.x * blockDim.x + threadIdx.x) >> 5;
    const int nwarps = (gridDim.x * blockDim.x) >> 5;

    const float ls     = __ldg(ls_ptr);
    const float scaler = 10.0f * ls * (float)SUBDIV;
    const float inv_ls = 1.0f / ls;

    for (int v = warp0; v < V; v += nwarps) {
        // --- per-lane neighbor (k = lane): distance, index, 3 bin weights ---
        const float dsq    = __ldg(distsq + (size_t)v * K_NEIGH + lane);
        const int   my_idx = __ldg(nidx   + (size_t)v * K_NEIGH + lane);
        const float d  = sqrtf(dsq + EPSV);
        const float t1 = d - inv_ls;
        const float t2 = d - 2.0f * inv_ls;
        float w0 = __expf(-scaler * d  * d);
        float w1 = __expf(-scaler * t1 * t1);
        float w2 = __expf(-scaler * t2 * t2);

        // --- warp-reduce denominators (full 32-lane sums) ---
        float s0 = w0, s1 = w1, s2 = w2;
        #pragma unroll
        for (int off = 16; off > 0; off >>= 1) {
            s0 += __shfl_xor_sync(FULLM, s0, off);
            s1 += __shfl_xor_sync(FULLM, s1, off);
            s2 += __shfl_xor_sync(FULLM, s2, off);
        }
        const float r0 = 1.0f / (s0 + EPSV);
        const float r1 = 1.0f / (s1 + EPSV);
        const float r2 = 1.0f / (s2 + EPSV);

        // --- gather loop: 2 neighbors per iteration (one per half-warp) ---
        float4 a0 = make_float4(0.f, 0.f, 0.f, 0.f);
        float4 a1 = make_float4(0.f, 0.f, 0.f, 0.f);
        float4 a2 = make_float4(0.f, 0.f, 0.f, 0.f);
        const float* fbase = features + (size_t)4 * t;

        int kj = half;                              // this half's neighbors: half, half+2, ...
        #pragma unroll
        for (int j = 0; j < K_NEIGH / 2; ++j, kj += 2) {
            const int   ik = __shfl_sync(FULLM, my_idx, kj);
            const float b0 = __shfl_sync(FULLM, w0, kj);
            const float b1 = __shfl_sync(FULLM, w1, kj);
            const float b2 = __shfl_sync(FULLM, w2, kj);
            const float4 f = *reinterpret_cast<const float4*>(fbase + (size_t)ik * F_DIM);
            a0.x = fmaf(b0, f.x, a0.x); a0.y = fmaf(b0, f.y, a0.y);
            a0.z = fmaf(b0, f.z, a0.z); a0.w = fmaf(b0, f.w, a0.w);
            a1.x = fmaf(b1, f.x, a1.x); a1.y = fmaf(b1, f.y, a1.y);
            a1.z = fmaf(b1, f.z, a1.z); a1.w = fmaf(b1, f.w, a1.w);
            a2.x = fmaf(b2, f.x, a2.x); a2.y = fmaf(b2, f.y, a2.y);
            a2.z = fmaf(b2, f.z, a2.z); a2.w = fmaf(b2, f.w, a2.w);
        }

        // --- combine even-k (half 0) and odd-k (half 1) partials ---
        a0.x += __shfl_xor_sync(FULLM, a0.x, 16); a0.y += __shfl_xor_sync(FULLM, a0.y, 16);
        a0.z += __shfl_xor_sync(FULLM, a0.z, 16); a0.w += __shfl_xor_sync(FULLM, a0.w, 16);
        a1.x += __shfl_xor_sync(FULLM, a1.x, 16); a1.y += __shfl_xor_sync(FULLM, a1.y, 16);
        a1.z += __shfl_xor_sync(FULLM, a1.z, 16); a1.w += __shfl_xor_sync(FULLM, a1.w, 16);
        a2.x += __shfl_xor_sync(FULLM, a2.x, 16); a2.y += __shfl_xor_sync(FULLM, a2.y, 16);
        a2.z += __shfl_xor_sync(FULLM, a2.z, 16); a2.w += __shfl_xor_sync(FULLM, a2.w, 16);

        // --- write (V, 3*F). Both halves hold identical sums; half 0 stores
        //     bins 0 and 2, half 1 stores bin 1 (each a contiguous 256B
        //     half-warp run of STG.128). ---
        float* obase = out + (size_t)v * OUT_F + 4 * t;
        if (half == 0) {
            *reinterpret_cast<float4*>(obase) =
                make_float4(a0.x * r0, a0.y * r0, a0.z * r0, a0.w * r0);
            *reinterpret_cast<float4*>(obase + 2 * F_DIM) =
                make_float4(a2.x * r2, a2.y * r2, a2.z * r2, a2.w * r2);
        } else {
            *reinterpret_cast<float4*>(obase + F_DIM) =
                make_float4(a1.x * r1, a1.y * r1, a1.z * r1, a1.w * r1);
        }
    }
}

extern "C" void kernel_launch(void* const* d_in, const int* in_sizes, int n_in,
                              void* d_out, int out_size)
{
    const float* features = (const float*)d_in[0];
    const float* distsq   = (const float*)d_in[1];
    const int*   nidx     = (const int*)  d_in[2];
    const float* ls       = (const float*)d_in[3];
    float*       out      = (float*)d_out;

    int V = out_size / OUT_F;
    if (V <= 0) V = in_sizes[1] / K_NEIGH;

    const int threads = 256;                 // 8 warps/block, 8 vertices/block
    int blocks = (V * 32 + threads - 1) / threads;
    if (blocks < 1) blocks = 1;
    softpixel_kernel<<<blocks, threads>>>(features, distsq, nidx, ls, out, V);
}